// round 1
// baseline (speedup 1.0000x reference)
#include <cuda_runtime.h>
#include <cuda_bf16.h>
#include <cstdint>

// Problem constants
#define S_DIM 16
#define P_DIM 65536
#define N_DIM 256
#define K_DIM 32

// ---------------------------------------------------------------------------
// Kernel 1: zero-fill the output (192 MiB). One float4 store per thread,
// exact cover (out elements = 3*256*65536 = 50331648 floats = 12582912 float4,
// divisible by 256).
// ---------------------------------------------------------------------------
__global__ void zero_fill_kernel(float4* __restrict__ out) {
    size_t i = (size_t)blockIdx.x * blockDim.x + threadIdx.x;
    out[i] = make_float4(0.f, 0.f, 0.f, 0.f);
}

// ---------------------------------------------------------------------------
// Kernel 2: scatter. One warp per row n. Lane k owns indices[n,k].
// Duplicate indices within a row are collapsed via __match_any_sync; the
// lowest lane of each match group writes out 1 - (1-v)^count for each of
// the 3 projection channels.
// ---------------------------------------------------------------------------
__global__ void scatter_kernel(const float4* __restrict__ schema_params, // [S, P] float4
                               const int* __restrict__ schema_ids,       // [N]
                               const int* __restrict__ indices,          // [N, K]
                               float* __restrict__ out)                  // [3, N, P]
{
    int warp_id = (blockIdx.x * blockDim.x + threadIdx.x) >> 5;
    int lane    = threadIdx.x & 31;
    if (warp_id >= N_DIM) return;

    int n   = warp_id;
    int p   = indices[n * K_DIM + lane];
    int sid = schema_ids[n];

    unsigned mask  = __match_any_sync(0xffffffffu, p);
    int      count = __popc(mask);
    bool     leader = (lane == (__ffs(mask) - 1));

    if (leader) {
        // schema_params[sid, p, 0..3]
        float4 sp = schema_params[(size_t)sid * P_DIM + p];
        // proj rows: c0 = f2+f3, c1 = f1, c2 = f3
        float v0 = sp.z + sp.w;
        float v1 = sp.y;
        float v2 = sp.w;

        float b0 = 1.0f - v0;
        float b1 = 1.0f - v1;
        float b2 = 1.0f - v2;

        // integer power, count in [1, 32]
        float r0 = b0, r1 = b1, r2 = b2;
        for (int i = 1; i < count; i++) { r0 *= b0; r1 *= b1; r2 *= b2; }

        size_t base = (size_t)n * P_DIM + p;
        const size_t CH = (size_t)N_DIM * P_DIM;
        out[base]          = 1.0f - r0;
        out[base + CH]     = 1.0f - r1;
        out[base + 2 * CH] = 1.0f - r2;
    }
}

extern "C" void kernel_launch(void* const* d_in, const int* in_sizes, int n_in,
                              void* d_out, int out_size) {
    const float4* schema_params = (const float4*)d_in[0];   // (16, 65536, 4) fp32
    const int*    schema_ids    = (const int*)d_in[1];      // (256,)
    const int*    indices       = (const int*)d_in[2];      // (256, 32)
    float*        out           = (float*)d_out;            // (3, 256, 65536) fp32

    // Zero fill: 50331648 floats = 12582912 float4; 12582912 / 256 = 49152 blocks
    const size_t n_vec = (size_t)3 * N_DIM * P_DIM / 4;
    const int threads = 256;
    const int blocks  = (int)(n_vec / threads);
    zero_fill_kernel<<<blocks, threads>>>((float4*)out);

    // Scatter: 256 warps = 8192 threads
    scatter_kernel<<<32, 256>>>(schema_params, schema_ids, indices, out);
}